// round 13
// baseline (speedup 1.0000x reference)
#include <cuda_runtime.h>
#include <math.h>
#include <stdint.h>

// ---------------------------------------------------------------------------
// Fused CNN, B=2048.
//  k0: w2,w3 -> fragment-ordered tf32
//  k2: conv1+pool (in-smem) + conv2+pool via mma.sync tf32   [k1 fused away]
//  k3a: conv3 via mma.sync tf32 (occ 3)
//  k3b: dense1+dense2+softmax (fp32 scalar)
// ---------------------------------------------------------------------------

#define BATCH 2048

__device__ float g_p2[BATCH * 64 * 7 * 7];     // conv2+pool out, [b][oc][49]
__device__ float g_c3[BATCH * 3136];           // conv3 out, NHWC-flattened
__device__ float g_w2f[9 * 4 * 8 * 32 * 2];    // w2 fragment-ordered, tf32
__device__ float g_w3f[9 * 8 * 8 * 32 * 2];    // w3 fragment-ordered, tf32

// ---------------- helpers ----------------
__device__ __forceinline__ unsigned long long pack2(float x) {
    unsigned long long r;
    asm("mov.b64 %0, {%1, %1};" : "=l"(r) : "f"(x));
    return r;
}
__device__ __forceinline__ void ffma2(unsigned long long& d,
                                      unsigned long long a,
                                      unsigned long long b) {
    asm("fma.rn.f32x2 %0, %1, %2, %0;" : "+l"(d) : "l"(a), "l"(b));
}
__device__ __forceinline__ void unpack2(unsigned long long v, float& lo, float& hi) {
    asm("mov.b64 {%0, %1}, %2;" : "=f"(lo), "=f"(hi) : "l"(v));
}
__device__ __forceinline__ float tf32r(float v) {
    float o;
    asm("cvt.rna.tf32.f32 %0, %1;" : "=f"(o) : "f"(v));
    return o;
}
__device__ __forceinline__ uint32_t smem_u32(const void* p) {
    uint32_t a;
    asm("{ .reg .u64 t; cvta.to.shared.u64 t, %1; cvt.u32.u64 %0, t; }"
        : "=r"(a) : "l"(p));
    return a;
}
__device__ __forceinline__ uint32_t lds_u32(uint32_t a) {
    uint32_t v;
    asm volatile("ld.shared.b32 %0, [%1];" : "=r"(v) : "r"(a));
    return v;
}
__device__ __forceinline__ void lds_v2u(uint32_t a, uint32_t& x, uint32_t& y) {
    asm volatile("ld.shared.v2.b32 {%0,%1}, [%2];" : "=r"(x), "=r"(y) : "r"(a));
}
__device__ __forceinline__ float lds_f32(uint32_t a) {
    float v;
    asm volatile("ld.shared.f32 %0, [%1];" : "=f"(v) : "r"(a));
    return v;
}
__device__ __forceinline__ void sts_f32(uint32_t a, float v) {
    asm volatile("st.shared.f32 [%0], %1;" :: "r"(a), "f"(v));
}
__device__ __forceinline__ void sts_v4(uint32_t a, float4 v) {
    asm volatile("st.shared.v4.f32 [%0], {%1,%2,%3,%4};"
                 :: "r"(a), "f"(v.x), "f"(v.y), "f"(v.z), "f"(v.w));
}

__device__ __forceinline__ void mma16n8k8(float* d, uint32_t a0, uint32_t a1,
                                          uint32_t a2, uint32_t a3,
                                          uint32_t b0, uint32_t b1) {
    asm volatile(
        "mma.sync.aligned.m16n8k8.row.col.f32.tf32.tf32.f32 "
        "{%0,%1,%2,%3}, {%4,%5,%6,%7}, {%8,%9}, {%0,%1,%2,%3};"
        : "+f"(d[0]), "+f"(d[1]), "+f"(d[2]), "+f"(d[3])
        : "r"(a0), "r"(a1), "r"(a2), "r"(a3), "r"(b0), "r"(b1));
}

// ---------------------------------------------------------------------------
// K0: fragment-order + tf32-round w2, w3.
// ---------------------------------------------------------------------------
__global__ void k0_prep(const float* __restrict__ w2, const float* __restrict__ w3) {
    int i = blockIdx.x * 256 + threadIdx.x;
    if (i < 18432) {
        int j    = i & 1;
        int lane = (i >> 1) & 31;
        int nt   = (i >> 6) & 7;
        int ks   = (i >> 9) & 3;
        int tap  = i >> 11;
        int t = lane & 3, g = lane >> 2;
        g_w2f[i] = tf32r(w2[tap * 2048 + (ks * 8 + t + 4 * j) * 64 + nt * 8 + g]);
    } else if (i < 55296) {
        int k    = i - 18432;
        int j    = k & 1;
        int lane = (k >> 1) & 31;
        int nt   = (k >> 6) & 7;
        int ks   = (k >> 9) & 7;
        int tap  = k >> 12;
        int t = lane & 3, g = lane >> 2;
        g_w3f[k] = tf32r(w3[tap * 4096 + (ks * 8 + t + 4 * j) * 64 + nt * 8 + g]);
    }
}

// ---------------------------------------------------------------------------
// K2: conv1(+pool) fused + conv2 via mma.sync tf32. One image per CTA.
// ---------------------------------------------------------------------------
#define K2_AP_BYTES  36864u
#define K2_WF_BYTES  73728u
#define K2_BS_OFF    (K2_AP_BYTES + K2_WF_BYTES)
#define K2_SMEM      (K2_BS_OFF + 256)

__global__ void __launch_bounds__(256, 2)
k2_conv12_mma(const float* __restrict__ x, const float* __restrict__ w1,
              const float* __restrict__ b1, const float* __restrict__ b2) {
    extern __shared__ float sm[];
    const uint32_t S0 = smem_u32(sm);
    const uint32_t A0 = S0;
    const uint32_t W0 = S0 + K2_AP_BYTES;
    const uint32_t BS = S0 + K2_BS_OFF;
    const uint32_t C0 = S0;            // epilogue alias
    // conv1 scratch aliased at start of weight region (overwritten later)
    const uint32_t XS  = W0;           // 900 floats (30x30 padded input)
    const uint32_t W1S = W0 + 3600;    // 288 floats
    const uint32_t B1S = W1S + 1152;   // 32 floats

    const int tid = threadIdx.x;
    const int b   = blockIdx.x;
    const int wid = tid >> 5;
    const int ln  = tid & 31;
    const int t   = ln & 3;
    const int g   = ln >> 2;

    // ---- phase 1a: zero Apad, stage padded input + w1 + b1 ----
    float4 z4 = make_float4(0.f, 0.f, 0.f, 0.f);
    for (int u = tid; u < 2304; u += 256) sts_v4(A0 + u * 16, z4);
    for (int i = tid; i < 900; i += 256) sts_f32(XS + i * 4, 0.0f);
    for (int i = tid; i < 288; i += 256) sts_f32(W1S + i * 4, w1[i]);   // FIXED
    if (tid < 32)  sts_f32(B1S + tid * 4, b1[tid]);
    __syncthreads();

    const float* xb = x + b * 784;
    for (int i = tid; i < 784; i += 256) {
        int y = i / 28, xx = i % 28;
        sts_f32(XS + (uint32_t)(((y + 1) * 30 + xx + 1) * 4), xb[i]);
    }
    __syncthreads();

    // ---- phase 1b: conv1 + relu + maxpool2 -> Apad (tf32) ----
    for (int i = tid; i < 6272; i += 256) {
        int ic = i / 196, p = i % 196;
        int py = p / 14, px = p % 14;
        float wk[9];
#pragma unroll
        for (int tt = 0; tt < 9; tt++) wk[tt] = lds_f32(W1S + (tt * 32 + ic) * 4);
        float bias = lds_f32(B1S + ic * 4);
        float m = 0.0f;
#pragma unroll
        for (int dy = 0; dy < 2; dy++) {
#pragma unroll
            for (int dx = 0; dx < 2; dx++) {
                int y = 2 * py + dy, xx = 2 * px + dx;
                float s = bias;
#pragma unroll
                for (int ky = 0; ky < 3; ky++)
#pragma unroll
                    for (int kx = 0; kx < 3; kx++)
                        s = fmaf(lds_f32(XS + (uint32_t)(((y + ky) * 30 + xx + kx) * 4)),
                                 wk[ky * 3 + kx], s);
                m = fmaxf(m, fmaxf(s, 0.0f));
            }
        }
        sts_f32(A0 + (uint32_t)((((py + 1) * 16 + px + 1) * 144) + ic * 4), tf32r(m));
    }
    __syncthreads();

    // ---- phase 2a: load w2 fragments (overwrites xs) + bias2 ----
    {
        const float4* src = (const float4*)g_w2f;
        for (int u = tid; u < 4608; u += 256) {
            float4 v = src[u];
            sts_v4(W0 + u * 16, v);
        }
    }
    if (tid < 64) sts_f32(BS + tid * 4, b2[tid]);
    __syncthreads();

    // ---- phase 2b: implicit-GEMM mainloop ----
    uint32_t bA[2][2];
#pragma unroll
    for (int mt = 0; mt < 2; mt++) {
        int r0 = (wid * 2 + mt) * 16 + g;
        int p0 = min(r0, 195);
        int p1 = min(r0 + 8, 195);
        bA[mt][0] = A0 + (uint32_t)(((p0 / 14) * 16 + p0 % 14) * 144 + t * 4);
        bA[mt][1] = A0 + (uint32_t)(((p1 / 14) * 16 + p1 % 14) * 144 + t * 4);
    }
    const uint32_t wfl = W0 + ln * 8;

    float acc[2][8][4];
#pragma unroll
    for (int mt = 0; mt < 2; mt++)
#pragma unroll
        for (int nt = 0; nt < 8; nt++)
#pragma unroll
            for (int j = 0; j < 4; j++) acc[mt][nt][j] = 0.0f;

    for (int tap = 0; tap < 9; tap++) {
        const uint32_t toff = (uint32_t)(((tap / 3) * 16 + tap % 3) * 144);
        const uint32_t wtap = wfl + (uint32_t)(tap * 8192);
#pragma unroll
        for (int ks = 0; ks < 4; ks++) {
            uint32_t a[2][4];
#pragma unroll
            for (int mt = 0; mt < 2; mt++) {
                uint32_t c0 = bA[mt][0] + toff + ks * 32;
                uint32_t c1 = bA[mt][1] + toff + ks * 32;
                a[mt][0] = lds_u32(c0);
                a[mt][1] = lds_u32(c1);
                a[mt][2] = lds_u32(c0 + 16);
                a[mt][3] = lds_u32(c1 + 16);
            }
            uint32_t bx[8], by[8];
            const uint32_t wks = wtap + ks * 2048;
#pragma unroll
            for (int nt = 0; nt < 8; nt++) lds_v2u(wks + nt * 256, bx[nt], by[nt]);
#pragma unroll
            for (int nt = 0; nt < 8; nt++) {
                mma16n8k8(acc[0][nt], a[0][0], a[0][1], a[0][2], a[0][3], bx[nt], by[nt]);
                mma16n8k8(acc[1][nt], a[1][0], a[1][1], a[1][2], a[1][3], bx[nt], by[nt]);
            }
        }
    }

    float bs0[8], bs1[8];
#pragma unroll
    for (int nt = 0; nt < 8; nt++) {
        bs0[nt] = lds_f32(BS + (nt * 8 + 2 * t) * 4);
        bs1[nt] = lds_f32(BS + (nt * 8 + 2 * t + 1) * 4);
    }
    __syncthreads();

#pragma unroll
    for (int mt = 0; mt < 2; mt++) {
        int r0 = (wid * 2 + mt) * 16 + g;
        int r1 = r0 + 8;
#pragma unroll
        for (int nt = 0; nt < 8; nt++) {
            int c = nt * 8 + 2 * t;
            if (r0 < 196) {
                uint32_t ad = C0 + (uint32_t)((r0 * 65 + c) * 4);
                sts_f32(ad,     fmaxf(acc[mt][nt][0] + bs0[nt], 0.0f));
                sts_f32(ad + 4, fmaxf(acc[mt][nt][1] + bs1[nt], 0.0f));
            }
            if (r1 < 196) {
                uint32_t ad = C0 + (uint32_t)((r1 * 65 + c) * 4);
                sts_f32(ad,     fmaxf(acc[mt][nt][2] + bs0[nt], 0.0f));
                sts_f32(ad + 4, fmaxf(acc[mt][nt][3] + bs1[nt], 0.0f));
            }
        }
    }
    __syncthreads();

    float* pout = g_p2 + (size_t)b * 3136;
    for (int i = tid; i < 3136; i += 256) {
        int oc = i / 49, pp = i % 49;
        int py = pp / 7, px = pp % 7;
        int p00 = (2 * py) * 14 + 2 * px;
        float v0 = lds_f32(C0 + (uint32_t)((p00 * 65 + oc) * 4));
        float v1 = lds_f32(C0 + (uint32_t)(((p00 + 1) * 65 + oc) * 4));
        float v2 = lds_f32(C0 + (uint32_t)(((p00 + 14) * 65 + oc) * 4));
        float v3 = lds_f32(C0 + (uint32_t)(((p00 + 15) * 65 + oc) * 4));
        pout[i] = fmaxf(fmaxf(v0, v1), fmaxf(v2, v3));
    }
}

// ---------------------------------------------------------------------------
// K3a: conv3 via mma.sync tf32. 2 images/CTA, smem 60.7KB -> occ 3.
// ---------------------------------------------------------------------------
#define K3_A_BYTES   44064u                       // 2*81*68*4
#define K3_W_OFF     K3_A_BYTES                   // 16384 single slab
#define K3_BS_OFF    (K3_A_BYTES + 16384u)        // 60448
#define K3_SMEM      (K3_BS_OFF + 256u)           // 60704

__global__ void __launch_bounds__(256, 3)
k3a_conv3_mma(const float* __restrict__ b3) {
    extern __shared__ float sm3[];
    const uint32_t S0 = smem_u32(sm3);
    const uint32_t A0 = S0;
    const uint32_t W0 = S0 + K3_W_OFF;
    const uint32_t BS = S0 + K3_BS_OFF;

    const int tid = threadIdx.x;
    const int b0  = blockIdx.x * 2;
    const int wid = tid >> 5;
    const int ln  = tid & 31;
    const int t   = ln & 3;
    const int g   = ln >> 2;

    float4 z4 = make_float4(0.f, 0.f, 0.f, 0.f);
    for (int u = tid; u < 2754; u += 256) sts_v4(A0 + u * 16, z4);
    if (tid < 64) sts_f32(BS + tid * 4, b3[tid]);
    __syncthreads();

#pragma unroll
    for (int img = 0; img < 2; img++) {
        const float* pin = g_p2 + (size_t)(b0 + img) * 3136;
        for (int i = tid; i < 3136; i += 256) {
            int ic = i / 49, p = i % 49;
            int y = p / 7, xx = p % 7;
            uint32_t addr = A0 +
                (uint32_t)((img * 5508 + ((y + 1) * 9 + xx + 1) * 68 + ic) * 4);
            sts_f32(addr, tf32r(pin[i]));
        }
    }

    {
        const float4* src = (const float4*)g_w3f + tid * 4;
        float4 r0 = src[0], r1 = src[1], r2 = src[2], r3 = src[3];
        uint32_t dst = W0 + tid * 64;
        sts_v4(dst,      r0); sts_v4(dst + 16, r1);
        sts_v4(dst + 32, r2); sts_v4(dst + 48, r3);
    }
    __syncthreads();

    const int img = wid >> 2;        // 0..1
    const int mt  = wid & 3;         // m-tile 0..3
    uint32_t bA0, bA1;
    {
        int r = mt * 16 + g;
        int p0 = min(r, 48);
        int p1 = min(r + 8, 48);
        bA0 = A0 + (uint32_t)((img * 5508 + ((p0 / 7) * 9 + p0 % 7) * 68) * 4) + t * 4;
        bA1 = A0 + (uint32_t)((img * 5508 + ((p1 / 7) * 9 + p1 % 7) * 68) * 4) + t * 4;
    }
    const uint32_t wfl = W0 + ln * 8;

    float acc[8][4];
#pragma unroll
    for (int nt = 0; nt < 8; nt++)
#pragma unroll
        for (int j = 0; j < 4; j++) acc[nt][j] = 0.0f;

    for (int tap = 0; tap < 9; tap++) {
        const uint32_t toff = (uint32_t)(((tap / 3) * 9 + tap % 3) * 272);

#pragma unroll
        for (int ks = 0; ks < 8; ks++) {
            uint32_t c0 = bA0 + toff + ks * 32;
            uint32_t c1 = bA1 + toff + ks * 32;
            uint32_t a0 = lds_u32(c0);
            uint32_t a1 = lds_u32(c1);
            uint32_t a2 = lds_u32(c0 + 16);
            uint32_t a3 = lds_u32(c1 + 16);
            uint32_t bx[8], by[8];
            const uint32_t wks = wfl + ks * 2048;
#pragma unroll
            for (int nt = 0; nt < 8; nt++) lds_v2u(wks + nt * 256, bx[nt], by[nt]);
#pragma unroll
            for (int nt = 0; nt < 8; nt++)
                mma16n8k8(acc[nt], a0, a1, a2, a3, bx[nt], by[nt]);
        }

        if (tap < 8) {
            __syncthreads();
            const float4* src = (const float4*)(g_w3f + (tap + 1) * 4096) + tid * 4;
            float4 r0 = src[0], r1 = src[1], r2 = src[2], r3 = src[3];
            uint32_t dst = W0 + tid * 64;
            sts_v4(dst,      r0); sts_v4(dst + 16, r1);
            sts_v4(dst + 32, r2); sts_v4(dst + 48, r3);
            __syncthreads();
        }
    }

    float bs0[8], bs1[8];
#pragma unroll
    for (int nt = 0; nt < 8; nt++) {
        bs0[nt] = lds_f32(BS + (nt * 8 + 2 * t) * 4);
        bs1[nt] = lds_f32(BS + (nt * 8 + 2 * t + 1) * 4);
    }
    float* cb = g_c3 + (size_t)(b0 + img) * 3136;
    {
        int r0 = mt * 16 + g;
        int r1 = r0 + 8;
#pragma unroll
        for (int nt = 0; nt < 8; nt++) {
            int c = nt * 8 + 2 * t;
            if (r0 < 49) {
                float2 o;
                o.x = fmaxf(acc[nt][0] + bs0[nt], 0.0f);
                o.y = fmaxf(acc[nt][1] + bs1[nt], 0.0f);
                *reinterpret_cast<float2*>(cb + r0 * 64 + c) = o;
            }
            if (r1 < 49) {
                float2 o;
                o.x = fmaxf(acc[nt][2] + bs0[nt], 0.0f);
                o.y = fmaxf(acc[nt][3] + bs1[nt], 0.0f);
                *reinterpret_cast<float2*>(cb + r1 * 64 + c) = o;
            }
        }
    }
}

// ---------------------------------------------------------------------------
// K3b: dense1 (3136->64, relu) + dense2(64->10) + softmax.
// ---------------------------------------------------------------------------
__global__ void __launch_bounds__(256)
k3b_dense(const float* __restrict__ wd1, const float* __restrict__ bd1,
          const float* __restrict__ wd2, const float* __restrict__ bd2,
          float* __restrict__ out) {
    __shared__ float As[8 * 196];
    __shared__ float Ws[196 * 64];
    __shared__ float hs[8 * 64];

    const int tid = threadIdx.x;
    const int b0  = blockIdx.x * 8;
    const int bl  = tid >> 5;
    const int ocp = tid & 31;

    unsigned long long acc0 = 0ULL, acc1 = 0ULL;

    for (int ch = 0; ch < 16; ch++) {
        for (int i = tid; i < 392; i += 256) {
            int r = i / 49, c = i % 49;
            reinterpret_cast<float4*>(As + r * 196)[c] =
                *reinterpret_cast<const float4*>(
                    g_c3 + (size_t)(b0 + r) * 3136 + ch * 196 + c * 4);
        }
        const float4* src = reinterpret_cast<const float4*>(
            wd1 + (size_t)(ch * 196) * 64);
        for (int i = tid; i < 3136; i += 256)
            reinterpret_cast<float4*>(Ws)[i] = src[i];
        __syncthreads();

        const float* arow = As + bl * 196;
        const unsigned long long* wp =
            reinterpret_cast<const unsigned long long*>(Ws) + ocp;
#pragma unroll 2
        for (int k = 0; k < 196; k += 2) {
            ffma2(acc0, pack2(arow[k]),     wp[(size_t)k * 32]);
            ffma2(acc1, pack2(arow[k + 1]), wp[(size_t)(k + 1) * 32]);
        }
        __syncthreads();
    }

    {
        float v0, v1, u0, u1;
        unpack2(acc0, v0, v1);
        unpack2(acc1, u0, u1);
        int oc0 = ocp * 2;
        hs[bl * 64 + oc0]     = fmaxf(v0 + u0 + bd1[oc0],     0.0f);
        hs[bl * 64 + oc0 + 1] = fmaxf(v1 + u1 + bd1[oc0 + 1], 0.0f);
    }
    __syncthreads();

    if (tid < 8) {
        const float* h = hs + tid * 64;
        float lg[10];
#pragma unroll
        for (int c = 0; c < 10; c++) {
            float s = bd2[c];
#pragma unroll
            for (int j = 0; j < 64; j++)
                s = fmaf(h[j], wd2[j * 10 + c], s);
            lg[c] = s;
        }
        float m = lg[0];
#pragma unroll
        for (int c = 1; c < 10; c++) m = fmaxf(m, lg[c]);
        float se = 0.0f;
#pragma unroll
        for (int c = 0; c < 10; c++) { lg[c] = expf(lg[c] - m); se += lg[c]; }
        float inv = 1.0f / se;
        float* o = out + (size_t)(b0 + tid) * 10;
#pragma unroll
        for (int c = 0; c < 10; c++) o[c] = lg[c] * inv;
    }
}

// ---------------------------------------------------------------------------
extern "C" void kernel_launch(void* const* d_in, const int* in_sizes, int n_in,
                              void* d_out, int out_size) {
    const float* x   = (const float*)d_in[0];
    const float* w1  = (const float*)d_in[1];
    const float* b1  = (const float*)d_in[2];
    const float* w2  = (const float*)d_in[3];
    const float* b2  = (const float*)d_in[4];
    const float* w3  = (const float*)d_in[5];
    const float* b3  = (const float*)d_in[6];
    const float* wd1 = (const float*)d_in[7];
    const float* bd1 = (const float*)d_in[8];
    const float* wd2 = (const float*)d_in[9];
    const float* bd2 = (const float*)d_in[10];
    float* out = (float*)d_out;

    cudaFuncSetAttribute(k2_conv12_mma, cudaFuncAttributeMaxDynamicSharedMemorySize, K2_SMEM);
    cudaFuncSetAttribute(k3a_conv3_mma, cudaFuncAttributeMaxDynamicSharedMemorySize, K3_SMEM);

    k0_prep<<<216, 256>>>(w2, w3);
    k2_conv12_mma<<<BATCH, 256, K2_SMEM>>>(x, w1, b1, b2);
    k3a_conv3_mma<<<BATCH / 2, 256, K3_SMEM>>>(b3);
    k3b_dense<<<BATCH / 8, 256>>>(wd1, bd1, wd2, bd2, out);
}

// round 14
// speedup vs baseline: 1.0551x; 1.0551x over previous
#include <cuda_runtime.h>
#include <math.h>
#include <stdint.h>

// ---------------------------------------------------------------------------
// Fused CNN, B=2048.
//  k0: w2,w3,wd1 -> fragment-ordered tf32
//  k2: conv1+pool (in-smem, reg-cached wk) + conv2+pool via mma.sync tf32
//  k3a: conv3 via mma.sync tf32 (occ 3)
//  k3b: dense1 via mma.sync tf32 (reg double-buffered B) + dense2 + softmax
// ---------------------------------------------------------------------------

#define BATCH 2048

__device__ float g_p2[BATCH * 64 * 7 * 7];     // conv2+pool out, [b][oc][49]
__device__ float g_c3[BATCH * 3136];           // conv3 out, NHWC-flattened
__device__ float g_w2f[9 * 4 * 8 * 32 * 2];    // w2 fragment-ordered, tf32
__device__ float g_w3f[9 * 8 * 8 * 32 * 2];    // w3 fragment-ordered, tf32
__device__ float g_wd1f[392 * 8 * 64];         // wd1 fragment-ordered, tf32

// ---------------- helpers ----------------
__device__ __forceinline__ float tf32r(float v) {
    float o;
    asm("cvt.rna.tf32.f32 %0, %1;" : "=f"(o) : "f"(v));
    return o;
}
__device__ __forceinline__ uint32_t smem_u32(const void* p) {
    uint32_t a;
    asm("{ .reg .u64 t; cvta.to.shared.u64 t, %1; cvt.u32.u64 %0, t; }"
        : "=r"(a) : "l"(p));
    return a;
}
__device__ __forceinline__ uint32_t lds_u32(uint32_t a) {
    uint32_t v;
    asm volatile("ld.shared.b32 %0, [%1];" : "=r"(v) : "r"(a));
    return v;
}
__device__ __forceinline__ void lds_v2u(uint32_t a, uint32_t& x, uint32_t& y) {
    asm volatile("ld.shared.v2.b32 {%0,%1}, [%2];" : "=r"(x), "=r"(y) : "r"(a));
}
__device__ __forceinline__ float lds_f32(uint32_t a) {
    float v;
    asm volatile("ld.shared.f32 %0, [%1];" : "=f"(v) : "r"(a));
    return v;
}
__device__ __forceinline__ void sts_f32(uint32_t a, float v) {
    asm volatile("st.shared.f32 [%0], %1;" :: "r"(a), "f"(v));
}
__device__ __forceinline__ void sts_v4(uint32_t a, float4 v) {
    asm volatile("st.shared.v4.f32 [%0], {%1,%2,%3,%4};"
                 :: "r"(a), "f"(v.x), "f"(v.y), "f"(v.z), "f"(v.w));
}

__device__ __forceinline__ void mma16n8k8(float* d, uint32_t a0, uint32_t a1,
                                          uint32_t a2, uint32_t a3,
                                          uint32_t b0, uint32_t b1) {
    asm volatile(
        "mma.sync.aligned.m16n8k8.row.col.f32.tf32.tf32.f32 "
        "{%0,%1,%2,%3}, {%4,%5,%6,%7}, {%8,%9}, {%0,%1,%2,%3};"
        : "+f"(d[0]), "+f"(d[1]), "+f"(d[2]), "+f"(d[3])
        : "r"(a0), "r"(a1), "r"(a2), "r"(a3), "r"(b0), "r"(b1));
}

// ---------------------------------------------------------------------------
// K0: fragment-order + tf32-round w2, w3, wd1.
// frag[(ksIdx*8+nt)*64 + lane*2 + j] = W[k = ks*8+t+4j][oc = nt*8+g], lane=4g+t
// ---------------------------------------------------------------------------
__global__ void k0_prep(const float* __restrict__ w2, const float* __restrict__ w3,
                        const float* __restrict__ wd1) {
    int i = blockIdx.x * 256 + threadIdx.x;
    if (i < 18432) {
        int j    = i & 1;
        int lane = (i >> 1) & 31;
        int nt   = (i >> 6) & 7;
        int ks   = (i >> 9) & 3;
        int tap  = i >> 11;
        int t = lane & 3, g = lane >> 2;
        g_w2f[i] = tf32r(w2[tap * 2048 + (ks * 8 + t + 4 * j) * 64 + nt * 8 + g]);
    } else if (i < 55296) {
        int k    = i - 18432;
        int j    = k & 1;
        int lane = (k >> 1) & 31;
        int nt   = (k >> 6) & 7;
        int ks   = (k >> 9) & 7;
        int tap  = k >> 12;
        int t = lane & 3, g = lane >> 2;
        g_w3f[k] = tf32r(w3[tap * 4096 + (ks * 8 + t + 4 * j) * 64 + nt * 8 + g]);
    } else if (i < 256000) {
        int m    = i - 55296;
        int j    = m & 1;
        int lane = (m >> 1) & 31;
        int nt   = (m >> 6) & 7;
        int ks   = m >> 9;               // 0..391
        int t = lane & 3, g = lane >> 2;
        g_wd1f[m] = tf32r(wd1[(size_t)(ks * 8 + t + 4 * j) * 64 + nt * 8 + g]);
    }
}

// ---------------------------------------------------------------------------
// K2: conv1(+pool, reg-cached weights) fused + conv2 via mma.sync tf32.
// ---------------------------------------------------------------------------
#define K2_AP_BYTES  36864u
#define K2_WF_BYTES  73728u
#define K2_BS_OFF    (K2_AP_BYTES + K2_WF_BYTES)
#define K2_SMEM      (K2_BS_OFF + 256)

__global__ void __launch_bounds__(256, 2)
k2_conv12_mma(const float* __restrict__ x, const float* __restrict__ w1,
              const float* __restrict__ b1, const float* __restrict__ b2) {
    extern __shared__ float sm[];
    const uint32_t S0 = smem_u32(sm);
    const uint32_t A0 = S0;
    const uint32_t W0 = S0 + K2_AP_BYTES;
    const uint32_t BS = S0 + K2_BS_OFF;
    const uint32_t C0 = S0;            // epilogue alias
    const uint32_t XS  = W0;           // 900 floats (30x30 padded input)
    const uint32_t W1S = W0 + 3600;    // 288 floats
    const uint32_t B1S = W1S + 1152;   // 32 floats

    const int tid = threadIdx.x;
    const int b   = blockIdx.x;
    const int wid = tid >> 5;
    const int ln  = tid & 31;
    const int t   = ln & 3;
    const int g   = ln >> 2;

    // ---- phase 1a: zero Apad, stage padded input + w1 + b1 ----
    float4 z4 = make_float4(0.f, 0.f, 0.f, 0.f);
    for (int u = tid; u < 2304; u += 256) sts_v4(A0 + u * 16, z4);
    for (int i = tid; i < 900; i += 256) sts_f32(XS + i * 4, 0.0f);
    for (int i = tid; i < 288; i += 256) sts_f32(W1S + i * 4, w1[i]);
    if (tid < 32)  sts_f32(B1S + tid * 4, b1[tid]);
    __syncthreads();

    const float* xb = x + b * 784;
    for (int i = tid; i < 784; i += 256) {
        int y = i / 28, xx = i % 28;
        sts_f32(XS + (uint32_t)(((y + 1) * 30 + xx + 1) * 4), xb[i]);
    }
    __syncthreads();

    // ---- phase 1b: conv1 + relu + maxpool2 -> Apad (tf32) ----
    // thread <-> fixed ic = tid>>3; weights cached in registers once.
    {
        const int ic = tid >> 3;          // 0..31
        const int p0 = tid & 7;           // position offset
        float wk[9];
#pragma unroll
        for (int tt = 0; tt < 9; tt++) wk[tt] = lds_f32(W1S + (tt * 32 + ic) * 4);
        const float bias = lds_f32(B1S + ic * 4);
        for (int p = p0; p < 196; p += 8) {
            int py = p / 14, px = p % 14;
            float m = 0.0f;
#pragma unroll
            for (int dy = 0; dy < 2; dy++) {
#pragma unroll
                for (int dx = 0; dx < 2; dx++) {
                    int y = 2 * py + dy, xx = 2 * px + dx;
                    float s = bias;
#pragma unroll
                    for (int ky = 0; ky < 3; ky++)
#pragma unroll
                        for (int kx = 0; kx < 3; kx++)
                            s = fmaf(lds_f32(XS + (uint32_t)(((y + ky) * 30 + xx + kx) * 4)),
                                     wk[ky * 3 + kx], s);
                    m = fmaxf(m, fmaxf(s, 0.0f));
                }
            }
            sts_f32(A0 + (uint32_t)((((py + 1) * 16 + px + 1) * 144) + ic * 4), tf32r(m));
        }
    }
    __syncthreads();

    // ---- phase 2a: load w2 fragments (overwrites xs) + bias2 ----
    {
        const float4* src = (const float4*)g_w2f;
        for (int u = tid; u < 4608; u += 256) {
            float4 v = src[u];
            sts_v4(W0 + u * 16, v);
        }
    }
    if (tid < 64) sts_f32(BS + tid * 4, b2[tid]);
    __syncthreads();

    // ---- phase 2b: implicit-GEMM mainloop ----
    uint32_t bA[2][2];
#pragma unroll
    for (int mt = 0; mt < 2; mt++) {
        int r0 = (wid * 2 + mt) * 16 + g;
        int p0 = min(r0, 195);
        int p1 = min(r0 + 8, 195);
        bA[mt][0] = A0 + (uint32_t)(((p0 / 14) * 16 + p0 % 14) * 144 + t * 4);
        bA[mt][1] = A0 + (uint32_t)(((p1 / 14) * 16 + p1 % 14) * 144 + t * 4);
    }
    const uint32_t wfl = W0 + ln * 8;

    float acc[2][8][4];
#pragma unroll
    for (int mt = 0; mt < 2; mt++)
#pragma unroll
        for (int nt = 0; nt < 8; nt++)
#pragma unroll
            for (int j = 0; j < 4; j++) acc[mt][nt][j] = 0.0f;

    for (int tap = 0; tap < 9; tap++) {
        const uint32_t toff = (uint32_t)(((tap / 3) * 16 + tap % 3) * 144);
        const uint32_t wtap = wfl + (uint32_t)(tap * 8192);
#pragma unroll
        for (int ks = 0; ks < 4; ks++) {
            uint32_t a[2][4];
#pragma unroll
            for (int mt = 0; mt < 2; mt++) {
                uint32_t c0 = bA[mt][0] + toff + ks * 32;
                uint32_t c1 = bA[mt][1] + toff + ks * 32;
                a[mt][0] = lds_u32(c0);
                a[mt][1] = lds_u32(c1);
                a[mt][2] = lds_u32(c0 + 16);
                a[mt][3] = lds_u32(c1 + 16);
            }
            uint32_t bx[8], by[8];
            const uint32_t wks = wtap + ks * 2048;
#pragma unroll
            for (int nt = 0; nt < 8; nt++) lds_v2u(wks + nt * 256, bx[nt], by[nt]);
#pragma unroll
            for (int nt = 0; nt < 8; nt++) {
                mma16n8k8(acc[0][nt], a[0][0], a[0][1], a[0][2], a[0][3], bx[nt], by[nt]);
                mma16n8k8(acc[1][nt], a[1][0], a[1][1], a[1][2], a[1][3], bx[nt], by[nt]);
            }
        }
    }

    float bs0[8], bs1[8];
#pragma unroll
    for (int nt = 0; nt < 8; nt++) {
        bs0[nt] = lds_f32(BS + (nt * 8 + 2 * t) * 4);
        bs1[nt] = lds_f32(BS + (nt * 8 + 2 * t + 1) * 4);
    }
    __syncthreads();

#pragma unroll
    for (int mt = 0; mt < 2; mt++) {
        int r0 = (wid * 2 + mt) * 16 + g;
        int r1 = r0 + 8;
#pragma unroll
        for (int nt = 0; nt < 8; nt++) {
            int c = nt * 8 + 2 * t;
            if (r0 < 196) {
                uint32_t ad = C0 + (uint32_t)((r0 * 65 + c) * 4);
                sts_f32(ad,     fmaxf(acc[mt][nt][0] + bs0[nt], 0.0f));
                sts_f32(ad + 4, fmaxf(acc[mt][nt][1] + bs1[nt], 0.0f));
            }
            if (r1 < 196) {
                uint32_t ad = C0 + (uint32_t)((r1 * 65 + c) * 4);
                sts_f32(ad,     fmaxf(acc[mt][nt][2] + bs0[nt], 0.0f));
                sts_f32(ad + 4, fmaxf(acc[mt][nt][3] + bs1[nt], 0.0f));
            }
        }
    }
    __syncthreads();

    float* pout = g_p2 + (size_t)b * 3136;
    for (int i = tid; i < 3136; i += 256) {
        int oc = i / 49, pp = i % 49;
        int py = pp / 7, px = pp % 7;
        int p00 = (2 * py) * 14 + 2 * px;
        float v0 = lds_f32(C0 + (uint32_t)((p00 * 65 + oc) * 4));
        float v1 = lds_f32(C0 + (uint32_t)(((p00 + 1) * 65 + oc) * 4));
        float v2 = lds_f32(C0 + (uint32_t)(((p00 + 14) * 65 + oc) * 4));
        float v3 = lds_f32(C0 + (uint32_t)(((p00 + 15) * 65 + oc) * 4));
        pout[i] = fmaxf(fmaxf(v0, v1), fmaxf(v2, v3));
    }
}

// ---------------------------------------------------------------------------
// K3a: conv3 via mma.sync tf32. 2 images/CTA, occ 3. (unchanged from R13)
// ---------------------------------------------------------------------------
#define K3_A_BYTES   44064u
#define K3_W_OFF     K3_A_BYTES
#define K3_BS_OFF    (K3_A_BYTES + 16384u)
#define K3_SMEM      (K3_BS_OFF + 256u)

__global__ void __launch_bounds__(256, 3)
k3a_conv3_mma(const float* __restrict__ b3) {
    extern __shared__ float sm3[];
    const uint32_t S0 = smem_u32(sm3);
    const uint32_t A0 = S0;
    const uint32_t W0 = S0 + K3_W_OFF;
    const uint32_t BS = S0 + K3_BS_OFF;

    const int tid = threadIdx.x;
    const int b0  = blockIdx.x * 2;
    const int wid = tid >> 5;
    const int ln  = tid & 31;
    const int t   = ln & 3;
    const int g   = ln >> 2;

    float4 z4 = make_float4(0.f, 0.f, 0.f, 0.f);
    for (int u = tid; u < 2754; u += 256) sts_v4(A0 + u * 16, z4);
    if (tid < 64) sts_f32(BS + tid * 4, b3[tid]);
    __syncthreads();

#pragma unroll
    for (int img = 0; img < 2; img++) {
        const float* pin = g_p2 + (size_t)(b0 + img) * 3136;
        for (int i = tid; i < 3136; i += 256) {
            int ic = i / 49, p = i % 49;
            int y = p / 7, xx = p % 7;
            uint32_t addr = A0 +
                (uint32_t)((img * 5508 + ((y + 1) * 9 + xx + 1) * 68 + ic) * 4);
            sts_f32(addr, tf32r(pin[i]));
        }
    }

    {
        const float4* src = (const float4*)g_w3f + tid * 4;
        float4 r0 = src[0], r1 = src[1], r2 = src[2], r3 = src[3];
        uint32_t dst = W0 + tid * 64;
        sts_v4(dst,      r0); sts_v4(dst + 16, r1);
        sts_v4(dst + 32, r2); sts_v4(dst + 48, r3);
    }
    __syncthreads();

    const int img = wid >> 2;
    const int mt  = wid & 3;
    uint32_t bA0, bA1;
    {
        int r = mt * 16 + g;
        int p0 = min(r, 48);
        int p1 = min(r + 8, 48);
        bA0 = A0 + (uint32_t)((img * 5508 + ((p0 / 7) * 9 + p0 % 7) * 68) * 4) + t * 4;
        bA1 = A0 + (uint32_t)((img * 5508 + ((p1 / 7) * 9 + p1 % 7) * 68) * 4) + t * 4;
    }
    const uint32_t wfl = W0 + ln * 8;

    float acc[8][4];
#pragma unroll
    for (int nt = 0; nt < 8; nt++)
#pragma unroll
        for (int j = 0; j < 4; j++) acc[nt][j] = 0.0f;

    for (int tap = 0; tap < 9; tap++) {
        const uint32_t toff = (uint32_t)(((tap / 3) * 9 + tap % 3) * 272);

#pragma unroll
        for (int ks = 0; ks < 8; ks++) {
            uint32_t c0 = bA0 + toff + ks * 32;
            uint32_t c1 = bA1 + toff + ks * 32;
            uint32_t a0 = lds_u32(c0);
            uint32_t a1 = lds_u32(c1);
            uint32_t a2 = lds_u32(c0 + 16);
            uint32_t a3 = lds_u32(c1 + 16);
            uint32_t bx[8], by[8];
            const uint32_t wks = wfl + ks * 2048;
#pragma unroll
            for (int nt = 0; nt < 8; nt++) lds_v2u(wks + nt * 256, bx[nt], by[nt]);
#pragma unroll
            for (int nt = 0; nt < 8; nt++)
                mma16n8k8(acc[nt], a0, a1, a2, a3, bx[nt], by[nt]);
        }

        if (tap < 8) {
            __syncthreads();
            const float4* src = (const float4*)(g_w3f + (tap + 1) * 4096) + tid * 4;
            float4 r0 = src[0], r1 = src[1], r2 = src[2], r3 = src[3];
            uint32_t dst = W0 + tid * 64;
            sts_v4(dst,      r0); sts_v4(dst + 16, r1);
            sts_v4(dst + 32, r2); sts_v4(dst + 48, r3);
            __syncthreads();
        }
    }

    float bs0[8], bs1[8];
#pragma unroll
    for (int nt = 0; nt < 8; nt++) {
        bs0[nt] = lds_f32(BS + (nt * 8 + 2 * t) * 4);
        bs1[nt] = lds_f32(BS + (nt * 8 + 2 * t + 1) * 4);
    }
    float* cb = g_c3 + (size_t)(b0 + img) * 3136;
    {
        int r0 = mt * 16 + g;
        int r1 = r0 + 8;
#pragma unroll
        for (int nt = 0; nt < 8; nt++) {
            int c = nt * 8 + 2 * t;
            if (r0 < 49) {
                float2 o;
                o.x = fmaxf(acc[nt][0] + bs0[nt], 0.0f);
                o.y = fmaxf(acc[nt][1] + bs1[nt], 0.0f);
                *reinterpret_cast<float2*>(cb + r0 * 64 + c) = o;
            }
            if (r1 < 49) {
                float2 o;
                o.x = fmaxf(acc[nt][2] + bs0[nt], 0.0f);
                o.y = fmaxf(acc[nt][3] + bs1[nt], 0.0f);
                *reinterpret_cast<float2*>(cb + r1 * 64 + c) = o;
            }
        }
    }
}

// ---------------------------------------------------------------------------
// K3b: dense1 via mma.sync tf32 + dense2 + softmax.
// Grid 128, M=16/CTA. Warp w handles ks % 8 == w; B frags LDG'd from g_wd1f
// with REGISTER DOUBLE BUFFERING (next ks prefetched during current MMAs).
// Partial C frags reduced through smem psum (aliases As).
// ---------------------------------------------------------------------------
#define D_PITCH  1572
#define D_AS_FLOATS (16 * D_PITCH)                 // 25152
#define D_SMEM   ((D_AS_FLOATS + 16 * 64) * 4)     // 104704

__global__ void __launch_bounds__(256)
k3b_dense_mma(const float* __restrict__ bd1,
              const float* __restrict__ wd2, const float* __restrict__ bd2,
              float* __restrict__ out) {
    extern __shared__ float smd[];
    const uint32_t S0 = smem_u32(smd);
    float* As   = smd;                     // 16 x 1572 (tf32)
    float* psum = smd;                     // alias: 8 x 1024 after compute
    float* hs   = smd + D_AS_FLOATS;       // 16 x 64

    const int tid = threadIdx.x;
    const int b0  = blockIdx.x * 16;
    const int w   = tid >> 5;
    const int ln  = tid & 31;
    const int t   = ln & 3;
    const int g   = ln >> 2;

    float acc[8][4];
#pragma unroll
    for (int nt = 0; nt < 8; nt++)
#pragma unroll
        for (int j = 0; j < 4; j++) acc[nt][j] = 0.0f;

    const uint32_t a00 = S0 + (uint32_t)((g * D_PITCH + t) * 4);
    const uint32_t a10 = S0 + (uint32_t)(((g + 8) * D_PITCH + t) * 4);

    for (int c = 0; c < 2; c++) {
        // stage A chunk: 16 rows x 1568 cols, coalesced, tf32
        for (int r = 0; r < 16; r++) {
            const float* src = g_c3 + (size_t)(b0 + r) * 3136 + c * 1568;
            float* dst = As + r * D_PITCH;
            for (int col = tid; col < 1568; col += 256)
                dst[col] = tf32r(src[col]);
        }
        __syncthreads();

        // compute: warp handles ksl (within chunk) with ksl % 8 == w,
        // double-buffered A+B fragments.
        int ksl = w;
        uint32_t ca0, ca1, ca2, ca3;
        float2 cb[8];
        {
            uint32_t kb = (uint32_t)(ksl * 32);
            ca0 = lds_u32(a00 + kb);
            ca1 = lds_u32(a10 + kb);
            ca2 = lds_u32(a00 + kb + 16);
            ca3 = lds_u32(a10 + kb + 16);
            const float2* wp = (const float2*)(g_wd1f +
                (size_t)((c * 196 + ksl) * 8) * 64) + ln;
#pragma unroll
            for (int nt = 0; nt < 8; nt++) cb[nt] = wp[nt * 32];
        }
        while (true) {
            int nxt = ksl + 8;
            uint32_t na0, na1, na2, na3;
            float2 nb[8];
            if (nxt < 196) {
                uint32_t kb = (uint32_t)(nxt * 32);
                na0 = lds_u32(a00 + kb);
                na1 = lds_u32(a10 + kb);
                na2 = lds_u32(a00 + kb + 16);
                na3 = lds_u32(a10 + kb + 16);
                const float2* wp = (const float2*)(g_wd1f +
                    (size_t)((c * 196 + nxt) * 8) * 64) + ln;
#pragma unroll
                for (int nt = 0; nt < 8; nt++) nb[nt] = wp[nt * 32];
            }
#pragma unroll
            for (int nt = 0; nt < 8; nt++)
                mma16n8k8(acc[nt], ca0, ca1, ca2, ca3,
                          __float_as_uint(cb[nt].x), __float_as_uint(cb[nt].y));
            if (nxt >= 196) break;
            ca0 = na0; ca1 = na1; ca2 = na2; ca3 = na3;
#pragma unroll
            for (int nt = 0; nt < 8; nt++) cb[nt] = nb[nt];
            ksl = nxt;
        }
        __syncthreads();   // done reading As before restage / psum alias
    }

    // store partial C frags to psum[w][16][64]
    {
        float* pb = psum + w * 1024;
#pragma unroll
        for (int nt = 0; nt < 8; nt++) {
            int cc = nt * 8 + 2 * t;
            *reinterpret_cast<float2*>(pb + g * 64 + cc) =
                make_float2(acc[nt][0], acc[nt][1]);
            *reinterpret_cast<float2*>(pb + (g + 8) * 64 + cc) =
                make_float2(acc[nt][2], acc[nt][3]);
        }
    }
    __syncthreads();

    // reduce 8 partials + bias + relu -> hs
    for (int i = tid; i < 1024; i += 256) {
        float s = 0.0f;
#pragma unroll
        for (int p = 0; p < 8; p++) s += psum[p * 1024 + i];
        hs[i] = fmaxf(s + bd1[i & 63], 0.0f);
    }
    __syncthreads();

    // dense2 + softmax
    if (tid < 16) {
        const float* h = hs + tid * 64;
        float lg[10];
#pragma unroll
        for (int c = 0; c < 10; c++) {
            float s = bd2[c];
#pragma unroll
            for (int j = 0; j < 64; j++)
                s = fmaf(h[j], wd2[j * 10 + c], s);
            lg[c] = s;
        }
        float m = lg[0];
#pragma unroll
        for (int c = 1; c < 10; c++) m = fmaxf(m, lg[c]);
        float se = 0.0f;
#pragma unroll
        for (int c = 0; c < 10; c++) { lg[c] = expf(lg[c] - m); se += lg[c]; }
        float inv = 1.0f / se;
        float* o = out + (size_t)(b0 + tid) * 10;
#pragma unroll
        for (int c = 0; c < 10; c++) o[c] = lg[c] * inv;
    }
}

// ---------------------------------------------------------------------------
extern "C" void kernel_launch(void* const* d_in, const int* in_sizes, int n_in,
                              void* d_out, int out_size) {
    const float* x   = (const float*)d_in[0];
    const float* w1  = (const float*)d_in[1];
    const float* b1  = (const float*)d_in[2];
    const float* w2  = (const float*)d_in[3];
    const float* b2  = (const float*)d_in[4];
    const float* w3  = (const float*)d_in[5];
    const float* b3  = (const float*)d_in[6];
    const float* wd1 = (const float*)d_in[7];
    const float* bd1 = (const float*)d_in[8];
    const float* wd2 = (const float*)d_in[9];
    const float* bd2 = (const float*)d_in[10];
    float* out = (float*)d_out;

    cudaFuncSetAttribute(k2_conv12_mma, cudaFuncAttributeMaxDynamicSharedMemorySize, K2_SMEM);
    cudaFuncSetAttribute(k3a_conv3_mma, cudaFuncAttributeMaxDynamicSharedMemorySize, K3_SMEM);
    cudaFuncSetAttribute(k3b_dense_mma, cudaFuncAttributeMaxDynamicSharedMemorySize, D_SMEM);

    k0_prep<<<1000, 256>>>(w2, w3, wd1);
    k2_conv12_mma<<<BATCH, 256, K2_SMEM>>>(x, w1, b1, b2);
    k3a_conv3_mma<<<BATCH / 2, 256, K3_SMEM>>>(b3);
    k3b_dense_mma<<<BATCH / 16, 256, D_SMEM>>>(bd1, wd2, bd2, out);
}

// round 16
// speedup vs baseline: 1.1235x; 1.0648x over previous
#include <cuda_runtime.h>
#include <math.h>
#include <stdint.h>

// ---------------------------------------------------------------------------
// Fused CNN, B=2048.
//  k0: w2,w3 -> fragment-ordered tf32
//  k2: conv1+pool (in-smem, reg-cached wk) + conv2+pool via mma.sync tf32
//  k3a: conv3 via mma.sync tf32 (occ 3)
//  k3b: dense1 scalar v2 (K-split warps, LDG weights, f32x2) + dense2 + softmax
// ---------------------------------------------------------------------------

#define BATCH 2048

__device__ float g_p2[BATCH * 64 * 7 * 7];     // conv2+pool out, [b][oc][49]
__device__ float g_c3[BATCH * 3136];           // conv3 out, NHWC-flattened
__device__ float g_w2f[9 * 4 * 8 * 32 * 2];    // w2 fragment-ordered, tf32
__device__ float g_w3f[9 * 8 * 8 * 32 * 2];    // w3 fragment-ordered, tf32

// ---------------- helpers ----------------
__device__ __forceinline__ unsigned long long pack2(float x) {
    unsigned long long r;
    asm("mov.b64 %0, {%1, %1};" : "=l"(r) : "f"(x));
    return r;
}
__device__ __forceinline__ void ffma2(unsigned long long& d,
                                      unsigned long long a,
                                      unsigned long long b) {
    asm("fma.rn.f32x2 %0, %1, %2, %0;" : "+l"(d) : "l"(a), "l"(b));
}
__device__ __forceinline__ void unpack2(unsigned long long v, float& lo, float& hi) {
    asm("mov.b64 {%0, %1}, %2;" : "=f"(lo), "=f"(hi) : "l"(v));
}
__device__ __forceinline__ float tf32r(float v) {
    float o;
    asm("cvt.rna.tf32.f32 %0, %1;" : "=f"(o) : "f"(v));
    return o;
}
__device__ __forceinline__ uint32_t smem_u32(const void* p) {
    uint32_t a;
    asm("{ .reg .u64 t; cvta.to.shared.u64 t, %1; cvt.u32.u64 %0, t; }"
        : "=r"(a) : "l"(p));
    return a;
}
__device__ __forceinline__ uint32_t lds_u32(uint32_t a) {
    uint32_t v;
    asm volatile("ld.shared.b32 %0, [%1];" : "=r"(v) : "r"(a));
    return v;
}
__device__ __forceinline__ void lds_v2u(uint32_t a, uint32_t& x, uint32_t& y) {
    asm volatile("ld.shared.v2.b32 {%0,%1}, [%2];" : "=r"(x), "=r"(y) : "r"(a));
}
__device__ __forceinline__ float lds_f32(uint32_t a) {
    float v;
    asm volatile("ld.shared.f32 %0, [%1];" : "=f"(v) : "r"(a));
    return v;
}
__device__ __forceinline__ void sts_f32(uint32_t a, float v) {
    asm volatile("st.shared.f32 [%0], %1;" :: "r"(a), "f"(v));
}
__device__ __forceinline__ void sts_v4(uint32_t a, float4 v) {
    asm volatile("st.shared.v4.f32 [%0], {%1,%2,%3,%4};"
                 :: "r"(a), "f"(v.x), "f"(v.y), "f"(v.z), "f"(v.w));
}

__device__ __forceinline__ void mma16n8k8(float* d, uint32_t a0, uint32_t a1,
                                          uint32_t a2, uint32_t a3,
                                          uint32_t b0, uint32_t b1) {
    asm volatile(
        "mma.sync.aligned.m16n8k8.row.col.f32.tf32.tf32.f32 "
        "{%0,%1,%2,%3}, {%4,%5,%6,%7}, {%8,%9}, {%0,%1,%2,%3};"
        : "+f"(d[0]), "+f"(d[1]), "+f"(d[2]), "+f"(d[3])
        : "r"(a0), "r"(a1), "r"(a2), "r"(a3), "r"(b0), "r"(b1));
}

// ---------------------------------------------------------------------------
// K0: fragment-order + tf32-round w2, w3.
// ---------------------------------------------------------------------------
__global__ void k0_prep(const float* __restrict__ w2, const float* __restrict__ w3) {
    int i = blockIdx.x * 256 + threadIdx.x;
    if (i < 18432) {
        int j    = i & 1;
        int lane = (i >> 1) & 31;
        int nt   = (i >> 6) & 7;
        int ks   = (i >> 9) & 3;
        int tap  = i >> 11;
        int t = lane & 3, g = lane >> 2;
        g_w2f[i] = tf32r(w2[tap * 2048 + (ks * 8 + t + 4 * j) * 64 + nt * 8 + g]);
    } else if (i < 55296) {
        int k    = i - 18432;
        int j    = k & 1;
        int lane = (k >> 1) & 31;
        int nt   = (k >> 6) & 7;
        int ks   = (k >> 9) & 7;
        int tap  = k >> 12;
        int t = lane & 3, g = lane >> 2;
        g_w3f[k] = tf32r(w3[tap * 4096 + (ks * 8 + t + 4 * j) * 64 + nt * 8 + g]);
    }
}

// ---------------------------------------------------------------------------
// K2: conv1(+pool, reg-cached weights) fused + conv2 via mma.sync tf32.
// ---------------------------------------------------------------------------
#define K2_AP_BYTES  36864u
#define K2_WF_BYTES  73728u
#define K2_BS_OFF    (K2_AP_BYTES + K2_WF_BYTES)
#define K2_SMEM      (K2_BS_OFF + 256)

__global__ void __launch_bounds__(256, 2)
k2_conv12_mma(const float* __restrict__ x, const float* __restrict__ w1,
              const float* __restrict__ b1, const float* __restrict__ b2) {
    extern __shared__ float sm[];
    const uint32_t S0 = smem_u32(sm);
    const uint32_t A0 = S0;
    const uint32_t W0 = S0 + K2_AP_BYTES;
    const uint32_t BS = S0 + K2_BS_OFF;
    const uint32_t C0 = S0;            // epilogue alias
    const uint32_t XS  = W0;           // 900 floats (30x30 padded input)
    const uint32_t W1S = W0 + 3600;    // 288 floats
    const uint32_t B1S = W1S + 1152;   // 32 floats

    const int tid = threadIdx.x;
    const int b   = blockIdx.x;
    const int wid = tid >> 5;
    const int ln  = tid & 31;
    const int t   = ln & 3;
    const int g   = ln >> 2;

    // ---- phase 1a ----
    float4 z4 = make_float4(0.f, 0.f, 0.f, 0.f);
    for (int u = tid; u < 2304; u += 256) sts_v4(A0 + u * 16, z4);
    for (int i = tid; i < 900; i += 256) sts_f32(XS + i * 4, 0.0f);
    for (int i = tid; i < 288; i += 256) sts_f32(W1S + i * 4, w1[i]);
    if (tid < 32)  sts_f32(B1S + tid * 4, b1[tid]);
    __syncthreads();

    const float* xb = x + b * 784;
    for (int i = tid; i < 784; i += 256) {
        int y = i / 28, xx = i % 28;
        sts_f32(XS + (uint32_t)(((y + 1) * 30 + xx + 1) * 4), xb[i]);
    }
    __syncthreads();

    // ---- phase 1b: conv1 + relu + maxpool2 -> Apad (tf32), reg-cached wk ----
    {
        const int ic = tid >> 3;
        const int p0 = tid & 7;
        float wk[9];
#pragma unroll
        for (int tt = 0; tt < 9; tt++) wk[tt] = lds_f32(W1S + (tt * 32 + ic) * 4);
        const float bias = lds_f32(B1S + ic * 4);
        for (int p = p0; p < 196; p += 8) {
            int py = p / 14, px = p % 14;
            float m = 0.0f;
#pragma unroll
            for (int dy = 0; dy < 2; dy++) {
#pragma unroll
                for (int dx = 0; dx < 2; dx++) {
                    int y = 2 * py + dy, xx = 2 * px + dx;
                    float s = bias;
#pragma unroll
                    for (int ky = 0; ky < 3; ky++)
#pragma unroll
                        for (int kx = 0; kx < 3; kx++)
                            s = fmaf(lds_f32(XS + (uint32_t)(((y + ky) * 30 + xx + kx) * 4)),
                                     wk[ky * 3 + kx], s);
                    m = fmaxf(m, fmaxf(s, 0.0f));
                }
            }
            sts_f32(A0 + (uint32_t)((((py + 1) * 16 + px + 1) * 144) + ic * 4), tf32r(m));
        }
    }
    __syncthreads();

    // ---- phase 2a ----
    {
        const float4* src = (const float4*)g_w2f;
        for (int u = tid; u < 4608; u += 256) {
            float4 v = src[u];
            sts_v4(W0 + u * 16, v);
        }
    }
    if (tid < 64) sts_f32(BS + tid * 4, b2[tid]);
    __syncthreads();

    // ---- phase 2b: implicit-GEMM mainloop ----
    uint32_t bA[2][2];
#pragma unroll
    for (int mt = 0; mt < 2; mt++) {
        int r0 = (wid * 2 + mt) * 16 + g;
        int p0 = min(r0, 195);
        int p1 = min(r0 + 8, 195);
        bA[mt][0] = A0 + (uint32_t)(((p0 / 14) * 16 + p0 % 14) * 144 + t * 4);
        bA[mt][1] = A0 + (uint32_t)(((p1 / 14) * 16 + p1 % 14) * 144 + t * 4);
    }
    const uint32_t wfl = W0 + ln * 8;

    float acc[2][8][4];
#pragma unroll
    for (int mt = 0; mt < 2; mt++)
#pragma unroll
        for (int nt = 0; nt < 8; nt++)
#pragma unroll
            for (int j = 0; j < 4; j++) acc[mt][nt][j] = 0.0f;

    for (int tap = 0; tap < 9; tap++) {
        const uint32_t toff = (uint32_t)(((tap / 3) * 16 + tap % 3) * 144);
        const uint32_t wtap = wfl + (uint32_t)(tap * 8192);
#pragma unroll
        for (int ks = 0; ks < 4; ks++) {
            uint32_t a[2][4];
#pragma unroll
            for (int mt = 0; mt < 2; mt++) {
                uint32_t c0 = bA[mt][0] + toff + ks * 32;
                uint32_t c1 = bA[mt][1] + toff + ks * 32;
                a[mt][0] = lds_u32(c0);
                a[mt][1] = lds_u32(c1);
                a[mt][2] = lds_u32(c0 + 16);
                a[mt][3] = lds_u32(c1 + 16);
            }
            uint32_t bx[8], by[8];
            const uint32_t wks = wtap + ks * 2048;
#pragma unroll
            for (int nt = 0; nt < 8; nt++) lds_v2u(wks + nt * 256, bx[nt], by[nt]);
#pragma unroll
            for (int nt = 0; nt < 8; nt++) {
                mma16n8k8(acc[0][nt], a[0][0], a[0][1], a[0][2], a[0][3], bx[nt], by[nt]);
                mma16n8k8(acc[1][nt], a[1][0], a[1][1], a[1][2], a[1][3], bx[nt], by[nt]);
            }
        }
    }

    float bs0[8], bs1[8];
#pragma unroll
    for (int nt = 0; nt < 8; nt++) {
        bs0[nt] = lds_f32(BS + (nt * 8 + 2 * t) * 4);
        bs1[nt] = lds_f32(BS + (nt * 8 + 2 * t + 1) * 4);
    }
    __syncthreads();

#pragma unroll
    for (int mt = 0; mt < 2; mt++) {
        int r0 = (wid * 2 + mt) * 16 + g;
        int r1 = r0 + 8;
#pragma unroll
        for (int nt = 0; nt < 8; nt++) {
            int c = nt * 8 + 2 * t;
            if (r0 < 196) {
                uint32_t ad = C0 + (uint32_t)((r0 * 65 + c) * 4);
                sts_f32(ad,     fmaxf(acc[mt][nt][0] + bs0[nt], 0.0f));
                sts_f32(ad + 4, fmaxf(acc[mt][nt][1] + bs1[nt], 0.0f));
            }
            if (r1 < 196) {
                uint32_t ad = C0 + (uint32_t)((r1 * 65 + c) * 4);
                sts_f32(ad,     fmaxf(acc[mt][nt][2] + bs0[nt], 0.0f));
                sts_f32(ad + 4, fmaxf(acc[mt][nt][3] + bs1[nt], 0.0f));
            }
        }
    }
    __syncthreads();

    float* pout = g_p2 + (size_t)b * 3136;
    for (int i = tid; i < 3136; i += 256) {
        int oc = i / 49, pp = i % 49;
        int py = pp / 7, px = pp % 7;
        int p00 = (2 * py) * 14 + 2 * px;
        float v0 = lds_f32(C0 + (uint32_t)((p00 * 65 + oc) * 4));
        float v1 = lds_f32(C0 + (uint32_t)(((p00 + 1) * 65 + oc) * 4));
        float v2 = lds_f32(C0 + (uint32_t)(((p00 + 14) * 65 + oc) * 4));
        float v3 = lds_f32(C0 + (uint32_t)(((p00 + 15) * 65 + oc) * 4));
        pout[i] = fmaxf(fmaxf(v0, v1), fmaxf(v2, v3));
    }
}

// ---------------------------------------------------------------------------
// K3a: conv3 via mma.sync tf32. 2 images/CTA, occ 3. (unchanged)
// ---------------------------------------------------------------------------
#define K3_A_BYTES   44064u
#define K3_W_OFF     K3_A_BYTES
#define K3_BS_OFF    (K3_A_BYTES + 16384u)
#define K3_SMEM      (K3_BS_OFF + 256u)

__global__ void __launch_bounds__(256, 3)
k3a_conv3_mma(const float* __restrict__ b3) {
    extern __shared__ float sm3[];
    const uint32_t S0 = smem_u32(sm3);
    const uint32_t A0 = S0;
    const uint32_t W0 = S0 + K3_W_OFF;
    const uint32_t BS = S0 + K3_BS_OFF;

    const int tid = threadIdx.x;
    const int b0  = blockIdx.x * 2;
    const int wid = tid >> 5;
    const int ln  = tid & 31;
    const int t   = ln & 3;
    const int g   = ln >> 2;

    float4 z4 = make_float4(0.f, 0.f, 0.f, 0.f);
    for (int u = tid; u < 2754; u += 256) sts_v4(A0 + u * 16, z4);
    if (tid < 64) sts_f32(BS + tid * 4, b3[tid]);
    __syncthreads();

#pragma unroll
    for (int img = 0; img < 2; img++) {
        const float* pin = g_p2 + (size_t)(b0 + img) * 3136;
        for (int i = tid; i < 3136; i += 256) {
            int ic = i / 49, p = i % 49;
            int y = p / 7, xx = p % 7;
            uint32_t addr = A0 +
                (uint32_t)((img * 5508 + ((y + 1) * 9 + xx + 1) * 68 + ic) * 4);
            sts_f32(addr, tf32r(pin[i]));
        }
    }

    {
        const float4* src = (const float4*)g_w3f + tid * 4;
        float4 r0 = src[0], r1 = src[1], r2 = src[2], r3 = src[3];
        uint32_t dst = W0 + tid * 64;
        sts_v4(dst,      r0); sts_v4(dst + 16, r1);
        sts_v4(dst + 32, r2); sts_v4(dst + 48, r3);
    }
    __syncthreads();

    const int img = wid >> 2;
    const int mt  = wid & 3;
    uint32_t bA0, bA1;
    {
        int r = mt * 16 + g;
        int p0 = min(r, 48);
        int p1 = min(r + 8, 48);
        bA0 = A0 + (uint32_t)((img * 5508 + ((p0 / 7) * 9 + p0 % 7) * 68) * 4) + t * 4;
        bA1 = A0 + (uint32_t)((img * 5508 + ((p1 / 7) * 9 + p1 % 7) * 68) * 4) + t * 4;
    }
    const uint32_t wfl = W0 + ln * 8;

    float acc[8][4];
#pragma unroll
    for (int nt = 0; nt < 8; nt++)
#pragma unroll
        for (int j = 0; j < 4; j++) acc[nt][j] = 0.0f;

    for (int tap = 0; tap < 9; tap++) {
        const uint32_t toff = (uint32_t)(((tap / 3) * 9 + tap % 3) * 272);

#pragma unroll
        for (int ks = 0; ks < 8; ks++) {
            uint32_t c0 = bA0 + toff + ks * 32;
            uint32_t c1 = bA1 + toff + ks * 32;
            uint32_t a0 = lds_u32(c0);
            uint32_t a1 = lds_u32(c1);
            uint32_t a2 = lds_u32(c0 + 16);
            uint32_t a3 = lds_u32(c1 + 16);
            uint32_t bx[8], by[8];
            const uint32_t wks = wfl + ks * 2048;
#pragma unroll
            for (int nt = 0; nt < 8; nt++) lds_v2u(wks + nt * 256, bx[nt], by[nt]);
#pragma unroll
            for (int nt = 0; nt < 8; nt++)
                mma16n8k8(acc[nt], a0, a1, a2, a3, bx[nt], by[nt]);
        }

        if (tap < 8) {
            __syncthreads();
            const float4* src = (const float4*)(g_w3f + (tap + 1) * 4096) + tid * 4;
            float4 r0 = src[0], r1 = src[1], r2 = src[2], r3 = src[3];
            uint32_t dst = W0 + tid * 64;
            sts_v4(dst,      r0); sts_v4(dst + 16, r1);
            sts_v4(dst + 32, r2); sts_v4(dst + 48, r3);
            __syncthreads();
        }
    }

    float bs0[8], bs1[8];
#pragma unroll
    for (int nt = 0; nt < 8; nt++) {
        bs0[nt] = lds_f32(BS + (nt * 8 + 2 * t) * 4);
        bs1[nt] = lds_f32(BS + (nt * 8 + 2 * t + 1) * 4);
    }
    float* cb = g_c3 + (size_t)(b0 + img) * 3136;
    {
        int r0 = mt * 16 + g;
        int r1 = r0 + 8;
#pragma unroll
        for (int nt = 0; nt < 8; nt++) {
            int c = nt * 8 + 2 * t;
            if (r0 < 49) {
                float2 o;
                o.x = fmaxf(acc[nt][0] + bs0[nt], 0.0f);
                o.y = fmaxf(acc[nt][1] + bs1[nt], 0.0f);
                *reinterpret_cast<float2*>(cb + r0 * 64 + c) = o;
            }
            if (r1 < 49) {
                float2 o;
                o.x = fmaxf(acc[nt][2] + bs0[nt], 0.0f);
                o.y = fmaxf(acc[nt][3] + bs1[nt], 0.0f);
                *reinterpret_cast<float2*>(cb + r1 * 64 + c) = o;
            }
        }
    }
}

// ---------------------------------------------------------------------------
// K3b v2: dense1 (3136->64, relu) + dense2 + softmax. M=8 rows/CTA, grid 256.
// Warps split K into 8 slices of 392: weights LDG.64'd from global ONCE per
// CTA (coalesced, L2-resident); A staged transposed At[k][8] pitch-12 so the
// per-k activation read is 2 broadcast ld.shared.v4. 8 f32x2 acc/thread;
// slice partials reduced via psum (aliases At after sync).
// ---------------------------------------------------------------------------
#define D3_CHUNK  784                        // k per chunk, 4 chunks
#define D3_PITCH  12                         // floats per k-row (8 used)
#define D3_AT_FLOATS (D3_CHUNK * D3_PITCH)   // 9408 floats = 37632 B

__global__ void __launch_bounds__(256)
k3b_dense(const float* __restrict__ wd1, const float* __restrict__ bd1,
          const float* __restrict__ wd2, const float* __restrict__ bd2,
          float* __restrict__ out) {
    __shared__ float At[D3_AT_FLOATS];       // also aliased as psum[8][8][64]
    __shared__ float hs[8 * 64];

    const int tid   = threadIdx.x;
    const int b0    = blockIdx.x * 8;
    const int slice = tid >> 5;              // warp's K slice (0..7)
    const int ocp   = tid & 31;              // oc pair: oc = 2*ocp, 2*ocp+1

    unsigned long long acc[8];
#pragma unroll
    for (int r = 0; r < 8; r++) acc[r] = 0ULL;

    const unsigned long long* wdp = (const unsigned long long*)wd1;

    for (int ch = 0; ch < 4; ch++) {
        // stage A transposed: g_c3[b0+r][ch*784 + k] -> At[k*12 + r]
        __syncthreads();
        for (int i = tid; i < 8 * D3_CHUNK; i += 256) {
            int r = i / D3_CHUNK, k = i % D3_CHUNK;
            At[k * D3_PITCH + r] =
                g_c3[(size_t)(b0 + r) * 3136 + ch * D3_CHUNK + k];
        }
        __syncthreads();

        // compute: warp handles k in [slice*98, slice*98+98)
        const int kl0 = slice * 98;
        const float4* at4 = (const float4*)At;
#pragma unroll 2
        for (int j = 0; j < 98; j++) {
            const int kl = kl0 + j;
            const int kg = ch * D3_CHUNK + kl;
            unsigned long long wv = wdp[(size_t)kg * 32 + ocp];
            float4 a0 = at4[kl * 3];
            float4 a1 = at4[kl * 3 + 1];
            ffma2(acc[0], pack2(a0.x), wv);
            ffma2(acc[1], pack2(a0.y), wv);
            ffma2(acc[2], pack2(a0.z), wv);
            ffma2(acc[3], pack2(a0.w), wv);
            ffma2(acc[4], pack2(a1.x), wv);
            ffma2(acc[5], pack2(a1.y), wv);
            ffma2(acc[6], pack2(a1.z), wv);
            ffma2(acc[7], pack2(a1.w), wv);
        }
    }
    __syncthreads();   // all warps done reading At before psum alias

    // psum[slice][row][64] aliases At (8*8*64 = 4096 floats < 9408)
    float* psum = At;
    {
        float* pb = psum + slice * 512;
#pragma unroll
        for (int r = 0; r < 8; r++) {
            float lo, hi;
            unpack2(acc[r], lo, hi);
            *reinterpret_cast<float2*>(pb + r * 64 + 2 * ocp) = make_float2(lo, hi);
        }
    }
    __syncthreads();

    // reduce 8 slices + bias + relu -> hs
    for (int i = tid; i < 512; i += 256) {
        float s = 0.0f;
#pragma unroll
        for (int p = 0; p < 8; p++) s += psum[p * 512 + i];
        hs[i] = fmaxf(s + bd1[i & 63], 0.0f);
    }
    __syncthreads();

    // dense2 + softmax
    if (tid < 8) {
        const float* h = hs + tid * 64;
        float lg[10];
#pragma unroll
        for (int c = 0; c < 10; c++) {
            float s = bd2[c];
#pragma unroll
            for (int j = 0; j < 64; j++)
                s = fmaf(h[j], wd2[j * 10 + c], s);
            lg[c] = s;
        }
        float m = lg[0];
#pragma unroll
        for (int c = 1; c < 10; c++) m = fmaxf(m, lg[c]);
        float se = 0.0f;
#pragma unroll
        for (int c = 0; c < 10; c++) { lg[c] = expf(lg[c] - m); se += lg[c]; }
        float inv = 1.0f / se;
        float* o = out + (size_t)(b0 + tid) * 10;
#pragma unroll
        for (int c = 0; c < 10; c++) o[c] = lg[c] * inv;
    }
}

// ---------------------------------------------------------------------------
extern "C" void kernel_launch(void* const* d_in, const int* in_sizes, int n_in,
                              void* d_out, int out_size) {
    const float* x   = (const float*)d_in[0];
    const float* w1  = (const float*)d_in[1];
    const float* b1  = (const float*)d_in[2];
    const float* w2  = (const float*)d_in[3];
    const float* b2  = (const float*)d_in[4];
    const float* w3  = (const float*)d_in[5];
    const float* b3  = (const float*)d_in[6];
    const float* wd1 = (const float*)d_in[7];
    const float* bd1 = (const float*)d_in[8];
    const float* wd2 = (const float*)d_in[9];
    const float* bd2 = (const float*)d_in[10];
    float* out = (float*)d_out;

    cudaFuncSetAttribute(k2_conv12_mma, cudaFuncAttributeMaxDynamicSharedMemorySize, K2_SMEM);
    cudaFuncSetAttribute(k3a_conv3_mma, cudaFuncAttributeMaxDynamicSharedMemorySize, K3_SMEM);

    k0_prep<<<216, 256>>>(w2, w3);
    k2_conv12_mma<<<BATCH, 256, K2_SMEM>>>(x, w1, b1, b2);
    k3a_conv3_mma<<<BATCH / 2, 256, K3_SMEM>>>(b3);
    k3b_dense<<<BATCH / 8, 256>>>(wd1, bd1, wd2, bd2, out);
}

// round 17
// speedup vs baseline: 1.1913x; 1.0604x over previous
#include <cuda_runtime.h>
#include <math.h>
#include <stdint.h>

// ---------------------------------------------------------------------------
// Fused CNN, B=2048.
//  k0: w2,w3 -> fragment-ordered tf32
//  k2: conv1+pool (in-smem, reg-cached wk) + conv2+pool via mma.sync tf32
//  k3a: conv3 via mma.sync tf32 (occ 3)
//  k3b: dense1 scalar v3 (K-split warps, MLP-7 batched LDG weights) + dense2
// ---------------------------------------------------------------------------

#define BATCH 2048

__device__ float g_p2[BATCH * 64 * 7 * 7];     // conv2+pool out, [b][oc][49]
__device__ float g_c3[BATCH * 3136];           // conv3 out, NHWC-flattened
__device__ float g_w2f[9 * 4 * 8 * 32 * 2];    // w2 fragment-ordered, tf32
__device__ float g_w3f[9 * 8 * 8 * 32 * 2];    // w3 fragment-ordered, tf32

// ---------------- helpers ----------------
__device__ __forceinline__ unsigned long long pack2(float x) {
    unsigned long long r;
    asm("mov.b64 %0, {%1, %1};" : "=l"(r) : "f"(x));
    return r;
}
__device__ __forceinline__ void ffma2(unsigned long long& d,
                                      unsigned long long a,
                                      unsigned long long b) {
    asm("fma.rn.f32x2 %0, %1, %2, %0;" : "+l"(d) : "l"(a), "l"(b));
}
__device__ __forceinline__ void unpack2(unsigned long long v, float& lo, float& hi) {
    asm("mov.b64 {%0, %1}, %2;" : "=f"(lo), "=f"(hi) : "l"(v));
}
__device__ __forceinline__ float tf32r(float v) {
    float o;
    asm("cvt.rna.tf32.f32 %0, %1;" : "=f"(o) : "f"(v));
    return o;
}
__device__ __forceinline__ uint32_t smem_u32(const void* p) {
    uint32_t a;
    asm("{ .reg .u64 t; cvta.to.shared.u64 t, %1; cvt.u32.u64 %0, t; }"
        : "=r"(a) : "l"(p));
    return a;
}
__device__ __forceinline__ uint32_t lds_u32(uint32_t a) {
    uint32_t v;
    asm volatile("ld.shared.b32 %0, [%1];" : "=r"(v) : "r"(a));
    return v;
}
__device__ __forceinline__ void lds_v2u(uint32_t a, uint32_t& x, uint32_t& y) {
    asm volatile("ld.shared.v2.b32 {%0,%1}, [%2];" : "=r"(x), "=r"(y) : "r"(a));
}
__device__ __forceinline__ float lds_f32(uint32_t a) {
    float v;
    asm volatile("ld.shared.f32 %0, [%1];" : "=f"(v) : "r"(a));
    return v;
}
__device__ __forceinline__ void sts_f32(uint32_t a, float v) {
    asm volatile("st.shared.f32 [%0], %1;" :: "r"(a), "f"(v));
}
__device__ __forceinline__ void sts_v4(uint32_t a, float4 v) {
    asm volatile("st.shared.v4.f32 [%0], {%1,%2,%3,%4};"
                 :: "r"(a), "f"(v.x), "f"(v.y), "f"(v.z), "f"(v.w));
}

__device__ __forceinline__ void mma16n8k8(float* d, uint32_t a0, uint32_t a1,
                                          uint32_t a2, uint32_t a3,
                                          uint32_t b0, uint32_t b1) {
    asm volatile(
        "mma.sync.aligned.m16n8k8.row.col.f32.tf32.tf32.f32 "
        "{%0,%1,%2,%3}, {%4,%5,%6,%7}, {%8,%9}, {%0,%1,%2,%3};"
        : "+f"(d[0]), "+f"(d[1]), "+f"(d[2]), "+f"(d[3])
        : "r"(a0), "r"(a1), "r"(a2), "r"(a3), "r"(b0), "r"(b1));
}

// ---------------------------------------------------------------------------
// K0: fragment-order + tf32-round w2, w3.
// ---------------------------------------------------------------------------
__global__ void k0_prep(const float* __restrict__ w2, const float* __restrict__ w3) {
    int i = blockIdx.x * 256 + threadIdx.x;
    if (i < 18432) {
        int j    = i & 1;
        int lane = (i >> 1) & 31;
        int nt   = (i >> 6) & 7;
        int ks   = (i >> 9) & 3;
        int tap  = i >> 11;
        int t = lane & 3, g = lane >> 2;
        g_w2f[i] = tf32r(w2[tap * 2048 + (ks * 8 + t + 4 * j) * 64 + nt * 8 + g]);
    } else if (i < 55296) {
        int k    = i - 18432;
        int j    = k & 1;
        int lane = (k >> 1) & 31;
        int nt   = (k >> 6) & 7;
        int ks   = (k >> 9) & 7;
        int tap  = k >> 12;
        int t = lane & 3, g = lane >> 2;
        g_w3f[k] = tf32r(w3[tap * 4096 + (ks * 8 + t + 4 * j) * 64 + nt * 8 + g]);
    }
}

// ---------------------------------------------------------------------------
// K2: conv1(+pool, reg-cached weights) fused + conv2 via mma.sync tf32.
// ---------------------------------------------------------------------------
#define K2_AP_BYTES  36864u
#define K2_WF_BYTES  73728u
#define K2_BS_OFF    (K2_AP_BYTES + K2_WF_BYTES)
#define K2_SMEM      (K2_BS_OFF + 256)

__global__ void __launch_bounds__(256, 2)
k2_conv12_mma(const float* __restrict__ x, const float* __restrict__ w1,
              const float* __restrict__ b1, const float* __restrict__ b2) {
    extern __shared__ float sm[];
    const uint32_t S0 = smem_u32(sm);
    const uint32_t A0 = S0;
    const uint32_t W0 = S0 + K2_AP_BYTES;
    const uint32_t BS = S0 + K2_BS_OFF;
    const uint32_t C0 = S0;            // epilogue alias
    const uint32_t XS  = W0;           // 900 floats (30x30 padded input)
    const uint32_t W1S = W0 + 3600;    // 288 floats
    const uint32_t B1S = W1S + 1152;   // 32 floats

    const int tid = threadIdx.x;
    const int b   = blockIdx.x;
    const int wid = tid >> 5;
    const int ln  = tid & 31;
    const int t   = ln & 3;
    const int g   = ln >> 2;

    // ---- phase 1a ----
    float4 z4 = make_float4(0.f, 0.f, 0.f, 0.f);
    for (int u = tid; u < 2304; u += 256) sts_v4(A0 + u * 16, z4);
    for (int i = tid; i < 900; i += 256) sts_f32(XS + i * 4, 0.0f);
    for (int i = tid; i < 288; i += 256) sts_f32(W1S + i * 4, w1[i]);
    if (tid < 32)  sts_f32(B1S + tid * 4, b1[tid]);
    __syncthreads();

    const float* xb = x + b * 784;
    for (int i = tid; i < 784; i += 256) {
        int y = i / 28, xx = i % 28;
        sts_f32(XS + (uint32_t)(((y + 1) * 30 + xx + 1) * 4), xb[i]);
    }
    __syncthreads();

    // ---- phase 1b: conv1 + relu + maxpool2 -> Apad (tf32), reg-cached wk ----
    {
        const int ic = tid >> 3;
        const int p0 = tid & 7;
        float wk[9];
#pragma unroll
        for (int tt = 0; tt < 9; tt++) wk[tt] = lds_f32(W1S + (tt * 32 + ic) * 4);
        const float bias = lds_f32(B1S + ic * 4);
        for (int p = p0; p < 196; p += 8) {
            int py = p / 14, px = p % 14;
            float m = 0.0f;
#pragma unroll
            for (int dy = 0; dy < 2; dy++) {
#pragma unroll
                for (int dx = 0; dx < 2; dx++) {
                    int y = 2 * py + dy, xx = 2 * px + dx;
                    float s = bias;
#pragma unroll
                    for (int ky = 0; ky < 3; ky++)
#pragma unroll
                        for (int kx = 0; kx < 3; kx++)
                            s = fmaf(lds_f32(XS + (uint32_t)(((y + ky) * 30 + xx + kx) * 4)),
                                     wk[ky * 3 + kx], s);
                    m = fmaxf(m, fmaxf(s, 0.0f));
                }
            }
            sts_f32(A0 + (uint32_t)((((py + 1) * 16 + px + 1) * 144) + ic * 4), tf32r(m));
        }
    }
    __syncthreads();

    // ---- phase 2a ----
    {
        const float4* src = (const float4*)g_w2f;
        for (int u = tid; u < 4608; u += 256) {
            float4 v = src[u];
            sts_v4(W0 + u * 16, v);
        }
    }
    if (tid < 64) sts_f32(BS + tid * 4, b2[tid]);
    __syncthreads();

    // ---- phase 2b: implicit-GEMM mainloop ----
    uint32_t bA[2][2];
#pragma unroll
    for (int mt = 0; mt < 2; mt++) {
        int r0 = (wid * 2 + mt) * 16 + g;
        int p0 = min(r0, 195);
        int p1 = min(r0 + 8, 195);
        bA[mt][0] = A0 + (uint32_t)(((p0 / 14) * 16 + p0 % 14) * 144 + t * 4);
        bA[mt][1] = A0 + (uint32_t)(((p1 / 14) * 16 + p1 % 14) * 144 + t * 4);
    }
    const uint32_t wfl = W0 + ln * 8;

    float acc[2][8][4];
#pragma unroll
    for (int mt = 0; mt < 2; mt++)
#pragma unroll
        for (int nt = 0; nt < 8; nt++)
#pragma unroll
            for (int j = 0; j < 4; j++) acc[mt][nt][j] = 0.0f;

    for (int tap = 0; tap < 9; tap++) {
        const uint32_t toff = (uint32_t)(((tap / 3) * 16 + tap % 3) * 144);
        const uint32_t wtap = wfl + (uint32_t)(tap * 8192);
#pragma unroll
        for (int ks = 0; ks < 4; ks++) {
            uint32_t a[2][4];
#pragma unroll
            for (int mt = 0; mt < 2; mt++) {
                uint32_t c0 = bA[mt][0] + toff + ks * 32;
                uint32_t c1 = bA[mt][1] + toff + ks * 32;
                a[mt][0] = lds_u32(c0);
                a[mt][1] = lds_u32(c1);
                a[mt][2] = lds_u32(c0 + 16);
                a[mt][3] = lds_u32(c1 + 16);
            }
            uint32_t bx[8], by[8];
            const uint32_t wks = wtap + ks * 2048;
#pragma unroll
            for (int nt = 0; nt < 8; nt++) lds_v2u(wks + nt * 256, bx[nt], by[nt]);
#pragma unroll
            for (int nt = 0; nt < 8; nt++) {
                mma16n8k8(acc[0][nt], a[0][0], a[0][1], a[0][2], a[0][3], bx[nt], by[nt]);
                mma16n8k8(acc[1][nt], a[1][0], a[1][1], a[1][2], a[1][3], bx[nt], by[nt]);
            }
        }
    }

    float bs0[8], bs1[8];
#pragma unroll
    for (int nt = 0; nt < 8; nt++) {
        bs0[nt] = lds_f32(BS + (nt * 8 + 2 * t) * 4);
        bs1[nt] = lds_f32(BS + (nt * 8 + 2 * t + 1) * 4);
    }
    __syncthreads();

#pragma unroll
    for (int mt = 0; mt < 2; mt++) {
        int r0 = (wid * 2 + mt) * 16 + g;
        int r1 = r0 + 8;
#pragma unroll
        for (int nt = 0; nt < 8; nt++) {
            int c = nt * 8 + 2 * t;
            if (r0 < 196) {
                uint32_t ad = C0 + (uint32_t)((r0 * 65 + c) * 4);
                sts_f32(ad,     fmaxf(acc[mt][nt][0] + bs0[nt], 0.0f));
                sts_f32(ad + 4, fmaxf(acc[mt][nt][1] + bs1[nt], 0.0f));
            }
            if (r1 < 196) {
                uint32_t ad = C0 + (uint32_t)((r1 * 65 + c) * 4);
                sts_f32(ad,     fmaxf(acc[mt][nt][2] + bs0[nt], 0.0f));
                sts_f32(ad + 4, fmaxf(acc[mt][nt][3] + bs1[nt], 0.0f));
            }
        }
    }
    __syncthreads();

    float* pout = g_p2 + (size_t)b * 3136;
    for (int i = tid; i < 3136; i += 256) {
        int oc = i / 49, pp = i % 49;
        int py = pp / 7, px = pp % 7;
        int p00 = (2 * py) * 14 + 2 * px;
        float v0 = lds_f32(C0 + (uint32_t)((p00 * 65 + oc) * 4));
        float v1 = lds_f32(C0 + (uint32_t)(((p00 + 1) * 65 + oc) * 4));
        float v2 = lds_f32(C0 + (uint32_t)(((p00 + 14) * 65 + oc) * 4));
        float v3 = lds_f32(C0 + (uint32_t)(((p00 + 15) * 65 + oc) * 4));
        pout[i] = fmaxf(fmaxf(v0, v1), fmaxf(v2, v3));
    }
}

// ---------------------------------------------------------------------------
// K3a: conv3 via mma.sync tf32. 2 images/CTA, occ 3. (unchanged)
// ---------------------------------------------------------------------------
#define K3_A_BYTES   44064u
#define K3_W_OFF     K3_A_BYTES
#define K3_BS_OFF    (K3_A_BYTES + 16384u)
#define K3_SMEM      (K3_BS_OFF + 256u)

__global__ void __launch_bounds__(256, 3)
k3a_conv3_mma(const float* __restrict__ b3) {
    extern __shared__ float sm3[];
    const uint32_t S0 = smem_u32(sm3);
    const uint32_t A0 = S0;
    const uint32_t W0 = S0 + K3_W_OFF;
    const uint32_t BS = S0 + K3_BS_OFF;

    const int tid = threadIdx.x;
    const int b0  = blockIdx.x * 2;
    const int wid = tid >> 5;
    const int ln  = tid & 31;
    const int t   = ln & 3;
    const int g   = ln >> 2;

    float4 z4 = make_float4(0.f, 0.f, 0.f, 0.f);
    for (int u = tid; u < 2754; u += 256) sts_v4(A0 + u * 16, z4);
    if (tid < 64) sts_f32(BS + tid * 4, b3[tid]);
    __syncthreads();

#pragma unroll
    for (int img = 0; img < 2; img++) {
        const float* pin = g_p2 + (size_t)(b0 + img) * 3136;
        for (int i = tid; i < 3136; i += 256) {
            int ic = i / 49, p = i % 49;
            int y = p / 7, xx = p % 7;
            uint32_t addr = A0 +
                (uint32_t)((img * 5508 + ((y + 1) * 9 + xx + 1) * 68 + ic) * 4);
            sts_f32(addr, tf32r(pin[i]));
        }
    }

    {
        const float4* src = (const float4*)g_w3f + tid * 4;
        float4 r0 = src[0], r1 = src[1], r2 = src[2], r3 = src[3];
        uint32_t dst = W0 + tid * 64;
        sts_v4(dst,      r0); sts_v4(dst + 16, r1);
        sts_v4(dst + 32, r2); sts_v4(dst + 48, r3);
    }
    __syncthreads();

    const int img = wid >> 2;
    const int mt  = wid & 3;
    uint32_t bA0, bA1;
    {
        int r = mt * 16 + g;
        int p0 = min(r, 48);
        int p1 = min(r + 8, 48);
        bA0 = A0 + (uint32_t)((img * 5508 + ((p0 / 7) * 9 + p0 % 7) * 68) * 4) + t * 4;
        bA1 = A0 + (uint32_t)((img * 5508 + ((p1 / 7) * 9 + p1 % 7) * 68) * 4) + t * 4;
    }
    const uint32_t wfl = W0 + ln * 8;

    float acc[8][4];
#pragma unroll
    for (int nt = 0; nt < 8; nt++)
#pragma unroll
        for (int j = 0; j < 4; j++) acc[nt][j] = 0.0f;

    for (int tap = 0; tap < 9; tap++) {
        const uint32_t toff = (uint32_t)(((tap / 3) * 9 + tap % 3) * 272);

#pragma unroll
        for (int ks = 0; ks < 8; ks++) {
            uint32_t c0 = bA0 + toff + ks * 32;
            uint32_t c1 = bA1 + toff + ks * 32;
            uint32_t a0 = lds_u32(c0);
            uint32_t a1 = lds_u32(c1);
            uint32_t a2 = lds_u32(c0 + 16);
            uint32_t a3 = lds_u32(c1 + 16);
            uint32_t bx[8], by[8];
            const uint32_t wks = wfl + ks * 2048;
#pragma unroll
            for (int nt = 0; nt < 8; nt++) lds_v2u(wks + nt * 256, bx[nt], by[nt]);
#pragma unroll
            for (int nt = 0; nt < 8; nt++)
                mma16n8k8(acc[nt], a0, a1, a2, a3, bx[nt], by[nt]);
        }

        if (tap < 8) {
            __syncthreads();
            const float4* src = (const float4*)(g_w3f + (tap + 1) * 4096) + tid * 4;
            float4 r0 = src[0], r1 = src[1], r2 = src[2], r3 = src[3];
            uint32_t dst = W0 + tid * 64;
            sts_v4(dst,      r0); sts_v4(dst + 16, r1);
            sts_v4(dst + 32, r2); sts_v4(dst + 48, r3);
            __syncthreads();
        }
    }

    float bs0[8], bs1[8];
#pragma unroll
    for (int nt = 0; nt < 8; nt++) {
        bs0[nt] = lds_f32(BS + (nt * 8 + 2 * t) * 4);
        bs1[nt] = lds_f32(BS + (nt * 8 + 2 * t + 1) * 4);
    }
    float* cb = g_c3 + (size_t)(b0 + img) * 3136;
    {
        int r0 = mt * 16 + g;
        int r1 = r0 + 8;
#pragma unroll
        for (int nt = 0; nt < 8; nt++) {
            int c = nt * 8 + 2 * t;
            if (r0 < 49) {
                float2 o;
                o.x = fmaxf(acc[nt][0] + bs0[nt], 0.0f);
                o.y = fmaxf(acc[nt][1] + bs1[nt], 0.0f);
                *reinterpret_cast<float2*>(cb + r0 * 64 + c) = o;
            }
            if (r1 < 49) {
                float2 o;
                o.x = fmaxf(acc[nt][2] + bs0[nt], 0.0f);
                o.y = fmaxf(acc[nt][3] + bs1[nt], 0.0f);
                *reinterpret_cast<float2*>(cb + r1 * 64 + c) = o;
            }
        }
    }
}

// ---------------------------------------------------------------------------
// K3b v3: dense1 + dense2 + softmax. M=8 rows/CTA, grid 256.
// Warps split K (8 slices of 392). Weights LDG.64 from global, BATCHED 7 AT
// A TIME (MLP 7 hides L2 latency). A staged transposed At[k][8] pitch-12.
// ---------------------------------------------------------------------------
#define D3_CHUNK  784                        // k per chunk, 4 chunks
#define D3_PITCH  12                         // floats per k-row (8 used)
#define D3_AT_FLOATS (D3_CHUNK * D3_PITCH)   // 9408 floats = 37632 B

__global__ void __launch_bounds__(256)
k3b_dense(const float* __restrict__ wd1, const float* __restrict__ bd1,
          const float* __restrict__ wd2, const float* __restrict__ bd2,
          float* __restrict__ out) {
    __shared__ float At[D3_AT_FLOATS];       // also aliased as psum[8][8][64]
    __shared__ float hs[8 * 64];

    const int tid   = threadIdx.x;
    const int b0    = blockIdx.x * 8;
    const int slice = tid >> 5;              // warp's K slice (0..7)
    const int ocp   = tid & 31;              // oc pair: oc = 2*ocp, 2*ocp+1

    unsigned long long acc[8];
#pragma unroll
    for (int r = 0; r < 8; r++) acc[r] = 0ULL;

    const unsigned long long* wdp = (const unsigned long long*)wd1;

    for (int ch = 0; ch < 4; ch++) {
        // stage A transposed: g_c3[b0+r][ch*784 + k] -> At[k*12 + r]
        __syncthreads();
        for (int i = tid; i < 8 * D3_CHUNK; i += 256) {
            int r = i / D3_CHUNK, k = i % D3_CHUNK;
            At[k * D3_PITCH + r] =
                g_c3[(size_t)(b0 + r) * 3136 + ch * D3_CHUNK + k];
        }
        __syncthreads();

        // compute: warp handles k in [slice*98, slice*98+98), 7-wide batches
        const int kl0 = slice * 98;
        const float4* at4 = (const float4*)At;
        const unsigned long long* wb =
            wdp + (size_t)(ch * D3_CHUNK + kl0) * 32 + ocp;
#pragma unroll 2
        for (int jj = 0; jj < 98; jj += 7) {
            unsigned long long wv[7];
#pragma unroll
            for (int u = 0; u < 7; u++)
                wv[u] = wb[(size_t)(jj + u) * 32];
#pragma unroll
            for (int u = 0; u < 7; u++) {
                const int kl = kl0 + jj + u;
                float4 a0 = at4[kl * 3];
                float4 a1 = at4[kl * 3 + 1];
                ffma2(acc[0], pack2(a0.x), wv[u]);
                ffma2(acc[1], pack2(a0.y), wv[u]);
                ffma2(acc[2], pack2(a0.z), wv[u]);
                ffma2(acc[3], pack2(a0.w), wv[u]);
                ffma2(acc[4], pack2(a1.x), wv[u]);
                ffma2(acc[5], pack2(a1.y), wv[u]);
                ffma2(acc[6], pack2(a1.z), wv[u]);
                ffma2(acc[7], pack2(a1.w), wv[u]);
            }
        }
    }
    __syncthreads();   // all warps done reading At before psum alias

    // psum[slice][row][64] aliases At
    float* psum = At;
    {
        float* pb = psum + slice * 512;
#pragma unroll
        for (int r = 0; r < 8; r++) {
            float lo, hi;
            unpack2(acc[r], lo, hi);
            *reinterpret_cast<float2*>(pb + r * 64 + 2 * ocp) = make_float2(lo, hi);
        }
    }
    __syncthreads();

    // reduce 8 slices + bias + relu -> hs
    for (int i = tid; i < 512; i += 256) {
        float s = 0.0f;
#pragma unroll
        for (int p = 0; p < 8; p++) s += psum[p * 512 + i];
        hs[i] = fmaxf(s + bd1[i & 63], 0.0f);
    }
    __syncthreads();

    // dense2 + softmax
    if (tid < 8) {
        const float* h = hs + tid * 64;
        float lg[10];
#pragma unroll
        for (int c = 0; c < 10; c++) {
            float s = bd2[c];
#pragma unroll
            for (int j = 0; j < 64; j++)
                s = fmaf(h[j], wd2[j * 10 + c], s);
            lg[c] = s;
        }
        float m = lg[0];
#pragma unroll
        for (int c = 1; c < 10; c++) m = fmaxf(m, lg[c]);
        float se = 0.0f;
#pragma unroll
        for (int c = 0; c < 10; c++) { lg[c] = expf(lg[c] - m); se += lg[c]; }
        float inv = 1.0f / se;
        float* o = out + (size_t)(b0 + tid) * 10;
#pragma unroll
        for (int c = 0; c < 10; c++) o[c] = lg[c] * inv;
    }
}

// ---------------------------------------------------------------------------
extern "C" void kernel_launch(void* const* d_in, const int* in_sizes, int n_in,
                              void* d_out, int out_size) {
    const float* x   = (const float*)d_in[0];
    const float* w1  = (const float*)d_in[1];
    const float* b1  = (const float*)d_in[2];
    const float* w2  = (const float*)d_in[3];
    const float* b2  = (const float*)d_in[4];
    const float* w3  = (const float*)d_in[5];
    const float* b3  = (const float*)d_in[6];
    const float* wd1 = (const float*)d_in[7];
    const float* bd1 = (const float*)d_in[8];
    const float* wd2 = (const float*)d_in[9];
    const float* bd2 = (const float*)d_in[10];
    float* out = (float*)d_out;

    cudaFuncSetAttribute(k2_conv12_mma, cudaFuncAttributeMaxDynamicSharedMemorySize, K2_SMEM);
    cudaFuncSetAttribute(k3a_conv3_mma, cudaFuncAttributeMaxDynamicSharedMemorySize, K3_SMEM);

    k0_prep<<<216, 256>>>(w2, w3);
    k2_conv12_mma<<<BATCH, 256, K2_SMEM>>>(x, w1, b1, b2);
    k3a_conv3_mma<<<BATCH / 2, 256, K3_SMEM>>>(b3);
    k3b_dense<<<BATCH / 8, 256>>>(wd1, bd1, wd2, bd2, out);
}